// round 1
// baseline (speedup 1.0000x reference)
#include <cuda_runtime.h>
#include <math.h>

#define HW      16384
#define BATCH   4
#define MTOK    256
#define HD      256
#define INNER   128
#define DH      64

#define TWO_PI 6.2831853071795864769f

// ---------------- scratch (device globals; no runtime allocation) ----------
__device__ float g_q  [HW * INNER];               // per-grid query features (shared over batch)
__device__ float g_h0 [HW * HD];
__device__ float g_h1 [HW * HD];
__device__ float g_t  [HW];
__device__ float g_k  [BATCH * 2 * MTOK * DH];    // [b][h][m][d]
__device__ float g_v  [BATCH * 2 * MTOK * DH];
__device__ float g_o  [BATCH * HW * INNER];
__device__ float g_mod[BATCH * HW * HD];

// ============================================================================
// K1: grid-shared features. 16 rows / block, 256 threads.
// fourier(Bq/Bl0/Bl1) -> xq -> q ; h0 ; h1 ; t
// ============================================================================
__global__ void k1_grid(const float* __restrict__ coords,
                        const float* __restrict__ Bq,
                        const float* __restrict__ Bl0,
                        const float* __restrict__ Bl1,
                        const float* __restrict__ qW,  const float* __restrict__ qb,
                        const float* __restrict__ toqW,
                        const float* __restrict__ bwW0, const float* __restrict__ bwb0,
                        const float* __restrict__ bwW1, const float* __restrict__ bwb1)
{
    __shared__ float four[3][16][64];   // [mat][row][feat]  (12 KB)
    __shared__ float xq[16][256];       // 16 KB
    const int tid  = threadIdx.x;
    const int base = blockIdx.x * 16;

    // Fourier features for the 3 bases
    for (int it = tid; it < 3 * 16 * 32; it += 256) {
        int mat = it >> 9;
        int rem = it & 511;
        int r   = rem >> 5;
        int i   = rem & 31;
        float x = coords[(base + r) * 2 + 0];
        float y = coords[(base + r) * 2 + 1];
        const float* Bm = (mat == 0) ? Bq : (mat == 1 ? Bl0 : Bl1);
        float proj = TWO_PI * (x * Bm[i * 2] + y * Bm[i * 2 + 1]);
        float s, c;
        sincosf(proj, &s, &c);
        four[mat][r][i]      = c;
        four[mat][r][i + 32] = s;
    }
    if (tid < 16) {
        float x = coords[(base + tid) * 2 + 0];
        float y = coords[(base + tid) * 2 + 1];
        int row = (int)(x * 16.0f); row = min(max(row, 0), 15);
        int col = (int)(y * 16.0f); col = min(max(col, 0), 15);
        g_t[base + tid] = (float)(row * 16 + col) * (1.0f / 256.0f);
    }
    __syncthreads();

    // xq = relu(four_q @ qW + qb)   (64 -> 256)
    {
        const int j = tid;
        float acc[16];
#pragma unroll
        for (int r = 0; r < 16; r++) acc[r] = 0.f;
        for (int k = 0; k < 64; k++) {
            float w = qW[k * 256 + j];
#pragma unroll
            for (int r = 0; r < 16; r++) acc[r] = fmaf(four[0][r][k], w, acc[r]);
        }
        float b = qb[j];
#pragma unroll
        for (int r = 0; r < 16; r++) xq[r][j] = fmaxf(acc[r] + b, 0.f);
    }
    __syncthreads();

    // q = xq @ toqW   (256 -> 128). Threads split: half rows each.
    {
        const int j    = tid & 127;
        const int half = tid >> 7;
        float acc[8];
#pragma unroll
        for (int r = 0; r < 8; r++) acc[r] = 0.f;
        for (int k = 0; k < 256; k++) {
            float w = toqW[k * 128 + j];
#pragma unroll
            for (int r = 0; r < 8; r++) acc[r] = fmaf(xq[half * 8 + r][k], w, acc[r]);
        }
#pragma unroll
        for (int r = 0; r < 8; r++) g_q[(base + half * 8 + r) * 128 + j] = acc[r];
    }

    // h0 / h1 = relu(four_l @ bwW + bwb)   (64 -> 256)
    {
        const int j = tid;
        float a0[16], a1[16];
#pragma unroll
        for (int r = 0; r < 16; r++) { a0[r] = 0.f; a1[r] = 0.f; }
        for (int k = 0; k < 64; k++) {
            float w0 = bwW0[k * 256 + j];
            float w1 = bwW1[k * 256 + j];
#pragma unroll
            for (int r = 0; r < 16; r++) {
                a0[r] = fmaf(four[1][r][k], w0, a0[r]);
                a1[r] = fmaf(four[2][r][k], w1, a1[r]);
            }
        }
        float b0 = bwb0[j], b1 = bwb1[j];
#pragma unroll
        for (int r = 0; r < 16; r++) {
            g_h0[(base + r) * 256 + j] = fmaxf(a0[r] + b0, 0.f);
            g_h1[(base + r) * 256 + j] = fmaxf(a1[r] + b1, 0.f);
        }
    }
}

// ============================================================================
// K2: kv = tokens @ tokvW, split into per-head k / v.  16 tokens / block.
// ============================================================================
__global__ void k2_kv(const float* __restrict__ tokens,
                      const float* __restrict__ tokvW)
{
    __shared__ float tok[16][256];
    const int tile = blockIdx.x;   // 0..15
    const int b    = blockIdx.y;   // 0..3
    const int tid  = threadIdx.x;

    const float* tb = tokens + (b * MTOK + tile * 16) * 256;
    for (int i = tid; i < 16 * 256; i += 256) tok[i >> 8][i & 255] = tb[i];
    __syncthreads();

    const int j = tid;
    float acc[16];
#pragma unroll
    for (int r = 0; r < 16; r++) acc[r] = 0.f;
    for (int k = 0; k < 256; k++) {
        float w = tokvW[k * 256 + j];
#pragma unroll
        for (int r = 0; r < 16; r++) acc[r] = fmaf(tok[r][k], w, acc[r]);
    }
#pragma unroll
    for (int r = 0; r < 16; r++) {
        int m = tile * 16 + r;
        if (j < 128) {
            int h = j >> 6, d = j & 63;
            g_k[((b * 2 + h) * MTOK + m) * DH + d] = acc[r];
        } else {
            int j2 = j - 128;
            int h = j2 >> 6, d = j2 & 63;
            g_v[((b * 2 + h) * MTOK + m) * DH + d] = acc[r];
        }
    }
}

// ============================================================================
// K3: attention with spatial bias. Block = (b, h, 128 query rows).
// k,v tiles SMEM-resident (128 KB). One thread per query row, online softmax.
// ============================================================================
__global__ void __launch_bounds__(128) k3_attn()
{
    extern __shared__ float sm[];
    float* ks = sm;                 // [256][64]
    float* vs = sm + MTOK * DH;     // [256][64]

    const int tile = blockIdx.x;
    const int h    = blockIdx.y;
    const int b    = blockIdx.z;
    const int tid  = threadIdx.x;

    const float* kg = g_k + (b * 2 + h) * MTOK * DH;
    const float* vg = g_v + (b * 2 + h) * MTOK * DH;
    for (int i = tid * 4; i < MTOK * DH; i += 128 * 4) {
        *(float4*)&ks[i] = *(const float4*)&kg[i];
        *(float4*)&vs[i] = *(const float4*)&vg[i];
    }
    __syncthreads();

    const int row = tile * 128 + tid;
    float q[64];
#pragma unroll
    for (int d4 = 0; d4 < 16; d4++)
        ((float4*)q)[d4] = ((const float4*)(g_q + row * 128 + h * 64))[d4];

    const float tt = g_t[row];

    float acc[64];
#pragma unroll
    for (int d = 0; d < 64; d++) acc[d] = 0.f;
    float Mx = -1e30f, S = 0.f;

    for (int m = 0; m < 256; m++) {
        float s0 = 0.f, s1 = 0.f, s2 = 0.f, s3 = 0.f;
#pragma unroll
        for (int d = 0; d < 64; d += 4) {
            s0 = fmaf(q[d + 0], ks[m * 64 + d + 0], s0);
            s1 = fmaf(q[d + 1], ks[m * 64 + d + 1], s1);
            s2 = fmaf(q[d + 2], ks[m * 64 + d + 2], s2);
            s3 = fmaf(q[d + 3], ks[m * 64 + d + 3], s3);
        }
        float pos  = ((float)m + 0.5f) * (1.0f / 256.0f);
        float diff = tt - pos;
        float s = (s0 + s1 + s2 + s3) * 0.125f - 10.0f * diff * diff;

        if (s > Mx) {
            float corr = __expf(Mx - s);
            S *= corr;
#pragma unroll
            for (int d = 0; d < 64; d++) acc[d] *= corr;
            Mx = s;
        }
        float p = __expf(s - Mx);
        S += p;
#pragma unroll
        for (int d = 0; d < 64; d++) acc[d] = fmaf(p, vs[m * 64 + d], acc[d]);
    }

    float inv = 1.0f / S;
    float* og = g_o + (b * HW + row) * 128 + h * 64;
#pragma unroll
    for (int d4 = 0; d4 < 16; d4++) {
        float4 o4;
        o4.x = acc[d4 * 4 + 0] * inv;
        o4.y = acc[d4 * 4 + 1] * inv;
        o4.z = acc[d4 * 4 + 2] * inv;
        o4.w = acc[d4 * 4 + 3] * inv;
        ((float4*)og)[d4] = o4;
    }
}

// ============================================================================
// K4: mod = o @ tooW + toob   (128 -> 256). 16 rows / block.
// ============================================================================
__global__ void k4_mod(const float* __restrict__ tooW,
                       const float* __restrict__ toob)
{
    __shared__ float osm[16][128];
    const int base = blockIdx.x * 16;       // rows in [0, B*HW)
    const int tid  = threadIdx.x;

    for (int i = tid; i < 16 * 128; i += 256) osm[i >> 7][i & 127] = g_o[base * 128 + i];
    __syncthreads();

    const int j = tid;
    float acc[16];
#pragma unroll
    for (int r = 0; r < 16; r++) acc[r] = 0.f;
    for (int k = 0; k < 128; k++) {
        float w = tooW[k * 256 + j];
#pragma unroll
        for (int r = 0; r < 16; r++) acc[r] = fmaf(osm[r][k], w, acc[r]);
    }
    float bb = toob[j];
#pragma unroll
    for (int r = 0; r < 16; r++) g_mod[(base + r) * 256 + j] = acc[r] + bb;
}

// ============================================================================
// K5: fused band-MLP stack + output projections. 16 rows / block.
//   m0 = relu(h0 + mod@modW0 + b); m1 = relu(h1 + mod@modW1 + b)
//   hv1 = relu((m0+m1)@hvW0 + b); out = m0@outW0 + hv1@outW1 + b0 + b1
// ============================================================================
__global__ void k5_mlp(const float* __restrict__ modW0, const float* __restrict__ modb0,
                       const float* __restrict__ modW1, const float* __restrict__ modb1,
                       const float* __restrict__ hvW0,  const float* __restrict__ hvb0,
                       const float* __restrict__ outW0, const float* __restrict__ outb0,
                       const float* __restrict__ outW1, const float* __restrict__ outb1,
                       float* __restrict__ out)
{
    extern __shared__ float sm[];
    float* s_mod = sm;            // 16*256
    float* s_m0  = sm + 4096;
    float* s_x   = sm + 8192;     // (m0+m1), later hv1

    const int base = blockIdx.x * 16;
    const int tid  = threadIdx.x;

    for (int i = tid; i < 4096; i += 256) s_mod[i] = g_mod[base * 256 + i];
    __syncthreads();

    const int j = tid;
    {
        float a0[16], a1[16];
#pragma unroll
        for (int r = 0; r < 16; r++) { a0[r] = 0.f; a1[r] = 0.f; }
        for (int k = 0; k < 256; k++) {
            float w0 = modW0[k * 256 + j];
            float w1 = modW1[k * 256 + j];
#pragma unroll
            for (int r = 0; r < 16; r++) {
                float mv = s_mod[r * 256 + k];
                a0[r] = fmaf(mv, w0, a0[r]);
                a1[r] = fmaf(mv, w1, a1[r]);
            }
        }
        float b0 = modb0[j], b1 = modb1[j];
        const int hwb = base & (HW - 1);    // tile never crosses batch boundary
#pragma unroll
        for (int r = 0; r < 16; r++) {
            float m0v = fmaxf(g_h0[(hwb + r) * 256 + j] + a0[r] + b0, 0.f);
            float m1v = fmaxf(g_h1[(hwb + r) * 256 + j] + a1[r] + b1, 0.f);
            s_m0[r * 256 + j] = m0v;
            s_x [r * 256 + j] = m0v + m1v;
        }
    }
    __syncthreads();

    {
        float ah[16];
#pragma unroll
        for (int r = 0; r < 16; r++) ah[r] = 0.f;
        for (int k = 0; k < 256; k++) {
            float w = hvW0[k * 256 + j];
#pragma unroll
            for (int r = 0; r < 16; r++) ah[r] = fmaf(s_x[r * 256 + k], w, ah[r]);
        }
        float bh = hvb0[j];
        __syncthreads();                    // done reading s_x before overwrite
#pragma unroll
        for (int r = 0; r < 16; r++) s_x[r * 256 + j] = fmaxf(ah[r] + bh, 0.f);
    }
    __syncthreads();

    // Output projections: warp w handles rows 2w, 2w+1 (3 channels each)
    const int warp = tid >> 5, lane = tid & 31;
#pragma unroll
    for (int r2 = 0; r2 < 2; r2++) {
        int r   = warp * 2 + r2;
        int row = base + r;
#pragma unroll
        for (int c = 0; c < 3; c++) {
            float p = 0.f;
            for (int k = lane; k < 256; k += 32)
                p += s_m0[r * 256 + k] * outW0[k * 3 + c]
                   + s_x [r * 256 + k] * outW1[k * 3 + c];
#pragma unroll
            for (int off = 16; off > 0; off >>= 1)
                p += __shfl_down_sync(0xffffffffu, p, off);
            if (lane == 0) out[row * 3 + c] = p + outb0[c] + outb1[c];
        }
    }
}

// ============================================================================
extern "C" void kernel_launch(void* const* d_in, const int* in_sizes, int n_in,
                              void* d_out, int out_size)
{
    const float* coords = (const float*)d_in[0];
    const float* tokens = (const float*)d_in[1];
    const float* B_q    = (const float*)d_in[2];
    const float* B_l0   = (const float*)d_in[3];
    const float* B_l1   = (const float*)d_in[4];
    const float* qW     = (const float*)d_in[5];
    const float* qb     = (const float*)d_in[6];
    const float* toqW   = (const float*)d_in[7];
    const float* tokvW  = (const float*)d_in[8];
    const float* tooW   = (const float*)d_in[9];
    const float* toob   = (const float*)d_in[10];
    const float* bwW0   = (const float*)d_in[11];
    const float* bwb0   = (const float*)d_in[12];
    const float* bwW1   = (const float*)d_in[13];
    const float* bwb1   = (const float*)d_in[14];
    const float* modW0  = (const float*)d_in[15];
    const float* modb0  = (const float*)d_in[16];
    const float* modW1  = (const float*)d_in[17];
    const float* modb1  = (const float*)d_in[18];
    const float* hvW0   = (const float*)d_in[19];
    const float* hvb0   = (const float*)d_in[20];
    const float* outW0  = (const float*)d_in[21];
    const float* outb0  = (const float*)d_in[22];
    const float* outW1  = (const float*)d_in[23];
    const float* outb1  = (const float*)d_in[24];
    float* out = (float*)d_out;

    cudaFuncSetAttribute(k3_attn, cudaFuncAttributeMaxDynamicSharedMemorySize, 131072);

    k1_grid<<<HW / 16, 256>>>(coords, B_q, B_l0, B_l1, qW, qb, toqW,
                              bwW0, bwb0, bwW1, bwb1);
    k2_kv<<<dim3(MTOK / 16, BATCH), 256>>>(tokens, tokvW);
    k3_attn<<<dim3(HW / 128, 2, BATCH), 128, 131072>>>();
    k4_mod<<<(BATCH * HW) / 16, 256>>>(tooW, toob);
    k5_mlp<<<(BATCH * HW) / 16, 256, 49152>>>(modW0, modb0, modW1, modb1,
                                              hvW0, hvb0, outW0, outb0, outW1, outb1,
                                              out);
}

// round 2
// speedup vs baseline: 1.1139x; 1.1139x over previous
#include <cuda_runtime.h>
#include <math.h>

#define HW      16384
#define BATCH   4
#define MTOK    256
#define HD      256
#define INNER   128
#define DH      64

#define TWO_PI 6.2831853071795864769f

typedef unsigned long long u64;

// ---- packed f32x2 helpers (sm_100+) ---------------------------------------
__device__ __forceinline__ u64 pack1(float v) {
    u64 r; asm("mov.b64 %0, {%1, %2};" : "=l"(r) : "f"(v), "f"(v)); return r;
}
__device__ __forceinline__ u64 ffma2(u64 a, u64 b, u64 c) {
    u64 d; asm("fma.rn.f32x2 %0, %1, %2, %3;" : "=l"(d) : "l"(a), "l"(b), "l"(c)); return d;
}
__device__ __forceinline__ u64 fmul2(u64 a, u64 b) {
    u64 d; asm("mul.rn.f32x2 %0, %1, %2;" : "=l"(d) : "l"(a), "l"(b)); return d;
}
__device__ __forceinline__ u64 fadd2(u64 a, u64 b) {
    u64 d; asm("add.rn.f32x2 %0, %1, %2;" : "=l"(d) : "l"(a), "l"(b)); return d;
}
__device__ __forceinline__ float2 unpack2(u64 v) {
    float2 f; asm("mov.b64 {%0, %1}, %2;" : "=f"(f.x), "=f"(f.y) : "l"(v)); return f;
}

// ---------------- scratch (device globals; no runtime allocation) ----------
__device__ float g_q  [HW * INNER];               // per-grid query features (shared over batch)
__device__ float g_h0 [HW * HD];
__device__ float g_h1 [HW * HD];
__device__ float g_t  [HW];
__device__ float g_k  [BATCH * 2 * MTOK * DH];    // [b][h][m][d]
__device__ float g_v  [BATCH * 2 * MTOK * DH];
__device__ float g_o  [BATCH * HW * INNER];

// ============================================================================
// K1: grid-shared features. 16 rows / block, 256 threads.
// ============================================================================
__global__ void k1_grid(const float* __restrict__ coords,
                        const float* __restrict__ Bq,
                        const float* __restrict__ Bl0,
                        const float* __restrict__ Bl1,
                        const float* __restrict__ qW,  const float* __restrict__ qb,
                        const float* __restrict__ toqW,
                        const float* __restrict__ bwW0, const float* __restrict__ bwb0,
                        const float* __restrict__ bwW1, const float* __restrict__ bwb1)
{
    __shared__ float four[3][16][64];
    __shared__ float xq[16][256];
    const int tid  = threadIdx.x;
    const int base = blockIdx.x * 16;

    for (int it = tid; it < 3 * 16 * 32; it += 256) {
        int mat = it >> 9;
        int rem = it & 511;
        int r   = rem >> 5;
        int i   = rem & 31;
        float x = coords[(base + r) * 2 + 0];
        float y = coords[(base + r) * 2 + 1];
        const float* Bm = (mat == 0) ? Bq : (mat == 1 ? Bl0 : Bl1);
        float proj = TWO_PI * (x * Bm[i * 2] + y * Bm[i * 2 + 1]);
        float s, c;
        sincosf(proj, &s, &c);
        four[mat][r][i]      = c;
        four[mat][r][i + 32] = s;
    }
    if (tid < 16) {
        float x = coords[(base + tid) * 2 + 0];
        float y = coords[(base + tid) * 2 + 1];
        int row = (int)(x * 16.0f); row = min(max(row, 0), 15);
        int col = (int)(y * 16.0f); col = min(max(col, 0), 15);
        g_t[base + tid] = (float)(row * 16 + col) * (1.0f / 256.0f);
    }
    __syncthreads();

    // xq = relu(four_q @ qW + qb)
    {
        const int j = tid;
        float acc[16];
#pragma unroll
        for (int r = 0; r < 16; r++) acc[r] = 0.f;
        for (int k = 0; k < 64; k++) {
            float w = qW[k * 256 + j];
#pragma unroll
            for (int r = 0; r < 16; r++) acc[r] = fmaf(four[0][r][k], w, acc[r]);
        }
        float b = qb[j];
#pragma unroll
        for (int r = 0; r < 16; r++) xq[r][j] = fmaxf(acc[r] + b, 0.f);
    }
    __syncthreads();

    // q = xq @ toqW
    {
        const int j    = tid & 127;
        const int half = tid >> 7;
        float acc[8];
#pragma unroll
        for (int r = 0; r < 8; r++) acc[r] = 0.f;
        for (int k = 0; k < 256; k++) {
            float w = toqW[k * 128 + j];
#pragma unroll
            for (int r = 0; r < 8; r++) acc[r] = fmaf(xq[half * 8 + r][k], w, acc[r]);
        }
#pragma unroll
        for (int r = 0; r < 8; r++) g_q[(base + half * 8 + r) * 128 + j] = acc[r];
    }

    // h0 / h1
    {
        const int j = tid;
        float a0[16], a1[16];
#pragma unroll
        for (int r = 0; r < 16; r++) { a0[r] = 0.f; a1[r] = 0.f; }
        for (int k = 0; k < 64; k++) {
            float w0 = bwW0[k * 256 + j];
            float w1 = bwW1[k * 256 + j];
#pragma unroll
            for (int r = 0; r < 16; r++) {
                a0[r] = fmaf(four[1][r][k], w0, a0[r]);
                a1[r] = fmaf(four[2][r][k], w1, a1[r]);
            }
        }
        float b0 = bwb0[j], b1 = bwb1[j];
#pragma unroll
        for (int r = 0; r < 16; r++) {
            g_h0[(base + r) * 256 + j] = fmaxf(a0[r] + b0, 0.f);
            g_h1[(base + r) * 256 + j] = fmaxf(a1[r] + b1, 0.f);
        }
    }
}

// ============================================================================
// K2: kv = tokens @ tokvW, split into per-head k / v.
// ============================================================================
__global__ void k2_kv(const float* __restrict__ tokens,
                      const float* __restrict__ tokvW)
{
    __shared__ float tok[16][256];
    const int tile = blockIdx.x;
    const int b    = blockIdx.y;
    const int tid  = threadIdx.x;

    const float* tb = tokens + (b * MTOK + tile * 16) * 256;
    for (int i = tid; i < 16 * 256; i += 256) tok[i >> 8][i & 255] = tb[i];
    __syncthreads();

    const int j = tid;
    float acc[16];
#pragma unroll
    for (int r = 0; r < 16; r++) acc[r] = 0.f;
    for (int k = 0; k < 256; k++) {
        float w = tokvW[k * 256 + j];
#pragma unroll
        for (int r = 0; r < 16; r++) acc[r] = fmaf(tok[r][k], w, acc[r]);
    }
#pragma unroll
    for (int r = 0; r < 16; r++) {
        int m = tile * 16 + r;
        if (j < 128) {
            int h = j >> 6, d = j & 63;
            g_k[((b * 2 + h) * MTOK + m) * DH + d] = acc[r];
        } else {
            int j2 = j - 128;
            int h = j2 >> 6, d = j2 & 63;
            g_v[((b * 2 + h) * MTOK + m) * DH + d] = acc[r];
        }
    }
}

// ============================================================================
// K3: attention with spatial bias. 256 threads/block (8 warps), f32x2 math.
// k,v SMEM-resident (128 KB). One thread per query row, online softmax.
// ============================================================================
__global__ void __launch_bounds__(256) k3_attn()
{
    extern __shared__ float sm[];
    float* ks = sm;                 // [256][64]
    float* vs = sm + MTOK * DH;     // [256][64]

    const int h   = blockIdx.y;
    const int b   = blockIdx.z;
    const int tid = threadIdx.x;

    const float* kg = g_k + (b * 2 + h) * MTOK * DH;
    const float* vg = g_v + (b * 2 + h) * MTOK * DH;
    for (int i = tid * 4; i < MTOK * DH; i += 256 * 4) {
        *(float4*)&ks[i] = *(const float4*)&kg[i];
        *(float4*)&vs[i] = *(const float4*)&vg[i];
    }
    __syncthreads();

    const int row = blockIdx.x * 256 + tid;
    u64 q2[32];
    {
        const ulonglong2* qp = (const ulonglong2*)(g_q + row * 128 + h * 64);
#pragma unroll
        for (int i = 0; i < 16; i++) { ulonglong2 t = qp[i]; q2[2*i] = t.x; q2[2*i+1] = t.y; }
    }
    const float tt = g_t[row];

    u64 acc[32];
#pragma unroll
    for (int i = 0; i < 32; i++) acc[i] = 0ULL;
    float Mx = -1e30f, S = 0.f;

    for (int m = 0; m < 256; m++) {
        const ulonglong2* kp = (const ulonglong2*)&ks[m * 64];
        u64 sA = 0, sB = 0, sC = 0, sD = 0;
#pragma unroll
        for (int i = 0; i < 16; i += 2) {
            ulonglong2 k0 = kp[i];
            ulonglong2 k1 = kp[i + 1];
            sA = ffma2(q2[2*i    ], k0.x, sA);
            sB = ffma2(q2[2*i + 1], k0.y, sB);
            sC = ffma2(q2[2*i + 2], k1.x, sC);
            sD = ffma2(q2[2*i + 3], k1.y, sD);
        }
        float2 sf = unpack2(fadd2(fadd2(sA, sB), fadd2(sC, sD)));
        float pos  = ((float)m + 0.5f) * (1.0f / 256.0f);
        float diff = tt - pos;
        float s = (sf.x + sf.y) * 0.125f - 10.0f * diff * diff;

        if (s > Mx) {
            float corr = __expf(Mx - s);
            S *= corr;
            u64 cp = pack1(corr);
#pragma unroll
            for (int i = 0; i < 32; i++) acc[i] = fmul2(acc[i], cp);
            Mx = s;
        }
        float p = __expf(s - Mx);
        S += p;
        u64 pp = pack1(p);
        const ulonglong2* vp = (const ulonglong2*)&vs[m * 64];
#pragma unroll
        for (int i = 0; i < 16; i++) {
            ulonglong2 v0 = vp[i];
            acc[2*i    ] = ffma2(pp, v0.x, acc[2*i    ]);
            acc[2*i + 1] = ffma2(pp, v0.y, acc[2*i + 1]);
        }
    }

    float inv = 1.0f / S;
    float* og = g_o + ((size_t)b * HW + row) * 128 + h * 64;
#pragma unroll
    for (int i = 0; i < 32; i++) {
        float2 f = unpack2(acc[i]);
        float2 o2; o2.x = f.x * inv; o2.y = f.y * inv;
        *(float2*)&og[2 * i] = o2;
    }
}

// ============================================================================
// K5: fused mod-projection + band-MLP stack + output projections.
// Block = 32 rows, 256 threads. Thread tile = 4 rows x 8 cols, f32x2 math.
//   mod = o@tooW + toob
//   m0 = relu(h0 + mod@modW0 + b); m1 = relu(h1 + mod@modW1 + b)
//   hv1 = relu((m0+m1)@hvW0 + b); out = m0@outW0 + hv1@outW1 + b0 + b1
// ============================================================================
__global__ void __launch_bounds__(256) k5_fused(
    const float* __restrict__ tooW,  const float* __restrict__ toob,
    const float* __restrict__ modW0, const float* __restrict__ modb0,
    const float* __restrict__ modW1, const float* __restrict__ modb1,
    const float* __restrict__ hvW0,  const float* __restrict__ hvb0,
    const float* __restrict__ outW0, const float* __restrict__ outb0,
    const float* __restrict__ outW1, const float* __restrict__ outb1,
    float* __restrict__ out)
{
    extern __shared__ float smem[];
    float* s_o  = smem;            // 32*128 = 4096 floats
    float* s_a  = smem + 4096;     // 32*256 (mod, later hv1)
    float* s_m0 = smem + 12288;    // 32*256
    float* s_x  = smem + 20480;    // 32*256

    const int tid  = threadIdx.x;
    const int base = blockIdx.x * 32;
    const int c0   = (tid & 31) * 8;
    const int r0   = (tid >> 5) * 4;

    for (int i = tid * 4; i < 32 * 128; i += 1024)
        *(float4*)&s_o[i] = *(const float4*)&g_o[(size_t)base * 128 + i];
    __syncthreads();

    // ---- stage 0: mod = o @ tooW + toob (K=128) ----
    {
        u64 a[4][4];
#pragma unroll
        for (int r = 0; r < 4; r++)
#pragma unroll
            for (int c = 0; c < 4; c++) a[r][c] = 0ULL;

        for (int k = 0; k < 128; k++) {
            ulonglong2 wa = *(const ulonglong2*)(tooW + k * 256 + c0);
            ulonglong2 wb = *(const ulonglong2*)(tooW + k * 256 + c0 + 4);
            u64 p[4];
#pragma unroll
            for (int r = 0; r < 4; r++) p[r] = pack1(s_o[(r0 + r) * 128 + k]);
#pragma unroll
            for (int r = 0; r < 4; r++) {
                a[r][0] = ffma2(p[r], wa.x, a[r][0]);
                a[r][1] = ffma2(p[r], wa.y, a[r][1]);
                a[r][2] = ffma2(p[r], wb.x, a[r][2]);
                a[r][3] = ffma2(p[r], wb.y, a[r][3]);
            }
        }
        ulonglong2 ba = *(const ulonglong2*)(toob + c0);
        ulonglong2 bb = *(const ulonglong2*)(toob + c0 + 4);
#pragma unroll
        for (int r = 0; r < 4; r++) {
            ulonglong2 o1, o2;
            o1.x = fadd2(a[r][0], ba.x); o1.y = fadd2(a[r][1], ba.y);
            o2.x = fadd2(a[r][2], bb.x); o2.y = fadd2(a[r][3], bb.y);
            *(ulonglong2*)&s_a[(r0 + r) * 256 + c0]     = o1;
            *(ulonglong2*)&s_a[(r0 + r) * 256 + c0 + 4] = o2;
        }
    }
    __syncthreads();

    // ---- stage 1: dual GEMM (modW0, modW1), combine with h0/h1 ----
    {
        u64 a0[4][4], a1[4][4];
#pragma unroll
        for (int r = 0; r < 4; r++)
#pragma unroll
            for (int c = 0; c < 4; c++) { a0[r][c] = 0ULL; a1[r][c] = 0ULL; }

        for (int k = 0; k < 256; k++) {
            ulonglong2 wa0 = *(const ulonglong2*)(modW0 + k * 256 + c0);
            ulonglong2 wb0 = *(const ulonglong2*)(modW0 + k * 256 + c0 + 4);
            ulonglong2 wa1 = *(const ulonglong2*)(modW1 + k * 256 + c0);
            ulonglong2 wb1 = *(const ulonglong2*)(modW1 + k * 256 + c0 + 4);
            u64 p[4];
#pragma unroll
            for (int r = 0; r < 4; r++) p[r] = pack1(s_a[(r0 + r) * 256 + k]);
#pragma unroll
            for (int r = 0; r < 4; r++) {
                a0[r][0] = ffma2(p[r], wa0.x, a0[r][0]);
                a0[r][1] = ffma2(p[r], wa0.y, a0[r][1]);
                a0[r][2] = ffma2(p[r], wb0.x, a0[r][2]);
                a0[r][3] = ffma2(p[r], wb0.y, a0[r][3]);
                a1[r][0] = ffma2(p[r], wa1.x, a1[r][0]);
                a1[r][1] = ffma2(p[r], wa1.y, a1[r][1]);
                a1[r][2] = ffma2(p[r], wb1.x, a1[r][2]);
                a1[r][3] = ffma2(p[r], wb1.y, a1[r][3]);
            }
        }
        const int hwr0 = (base & (HW - 1)) + r0;   // tiles never cross batch bound
        float4 b0a = *(const float4*)(modb0 + c0);
        float4 b0b = *(const float4*)(modb0 + c0 + 4);
        float4 b1a = *(const float4*)(modb1 + c0);
        float4 b1b = *(const float4*)(modb1 + c0 + 4);
        float bs0[8] = {b0a.x,b0a.y,b0a.z,b0a.w,b0b.x,b0b.y,b0b.z,b0b.w};
        float bs1[8] = {b1a.x,b1a.y,b1a.z,b1a.w,b1b.x,b1b.y,b1b.z,b1b.w};
#pragma unroll
        for (int r = 0; r < 4; r++) {
            const float* h0p = &g_h0[(size_t)(hwr0 + r) * 256 + c0];
            const float* h1p = &g_h1[(size_t)(hwr0 + r) * 256 + c0];
            float af0[8], af1[8];
#pragma unroll
            for (int c = 0; c < 4; c++) {
                float2 f0 = unpack2(a0[r][c]);
                float2 f1 = unpack2(a1[r][c]);
                af0[2*c] = f0.x; af0[2*c+1] = f0.y;
                af1[2*c] = f1.x; af1[2*c+1] = f1.y;
            }
            float m0v[8], xv[8];
#pragma unroll
            for (int i = 0; i < 8; i++) {
                float v0 = fmaxf(h0p[i] + af0[i] + bs0[i], 0.f);
                float v1 = fmaxf(h1p[i] + af1[i] + bs1[i], 0.f);
                m0v[i] = v0;
                xv[i]  = v0 + v1;
            }
            *(float4*)&s_m0[(r0 + r) * 256 + c0]     = *(float4*)&m0v[0];
            *(float4*)&s_m0[(r0 + r) * 256 + c0 + 4] = *(float4*)&m0v[4];
            *(float4*)&s_x [(r0 + r) * 256 + c0]     = *(float4*)&xv[0];
            *(float4*)&s_x [(r0 + r) * 256 + c0 + 4] = *(float4*)&xv[4];
        }
    }
    __syncthreads();

    // ---- stage 2: hv1 = relu(x @ hvW0 + hvb0), into s_a ----
    {
        u64 ah[4][4];
#pragma unroll
        for (int r = 0; r < 4; r++)
#pragma unroll
            for (int c = 0; c < 4; c++) ah[r][c] = 0ULL;

        for (int k = 0; k < 256; k++) {
            ulonglong2 wa = *(const ulonglong2*)(hvW0 + k * 256 + c0);
            ulonglong2 wb = *(const ulonglong2*)(hvW0 + k * 256 + c0 + 4);
            u64 p[4];
#pragma unroll
            for (int r = 0; r < 4; r++) p[r] = pack1(s_x[(r0 + r) * 256 + k]);
#pragma unroll
            for (int r = 0; r < 4; r++) {
                ah[r][0] = ffma2(p[r], wa.x, ah[r][0]);
                ah[r][1] = ffma2(p[r], wa.y, ah[r][1]);
                ah[r][2] = ffma2(p[r], wb.x, ah[r][2]);
                ah[r][3] = ffma2(p[r], wb.y, ah[r][3]);
            }
        }
        float4 bha = *(const float4*)(hvb0 + c0);
        float4 bhb = *(const float4*)(hvb0 + c0 + 4);
        float bh[8] = {bha.x,bha.y,bha.z,bha.w,bhb.x,bhb.y,bhb.z,bhb.w};
#pragma unroll
        for (int r = 0; r < 4; r++) {
            float hv[8];
#pragma unroll
            for (int c = 0; c < 4; c++) {
                float2 f = unpack2(ah[r][c]);
                hv[2*c]   = fmaxf(f.x + bh[2*c],   0.f);
                hv[2*c+1] = fmaxf(f.y + bh[2*c+1], 0.f);
            }
            *(float4*)&s_a[(r0 + r) * 256 + c0]     = *(float4*)&hv[0];
            *(float4*)&s_a[(r0 + r) * 256 + c0 + 4] = *(float4*)&hv[4];
        }
    }
    __syncthreads();

    // ---- stage 3: out = m0@outW0 + hv1@outW1 + biases ----
    {
        const int warp = tid >> 5, lane = tid & 31;
#pragma unroll
        for (int rr = 0; rr < 4; rr++) {
            int r = warp * 4 + rr;
            float p0 = 0.f, p1 = 0.f, p2 = 0.f;
            for (int k = lane; k < 256; k += 32) {
                float a  = s_m0[r * 256 + k];
                float bv = s_a [r * 256 + k];
                p0 += a * outW0[k * 3 + 0] + bv * outW1[k * 3 + 0];
                p1 += a * outW0[k * 3 + 1] + bv * outW1[k * 3 + 1];
                p2 += a * outW0[k * 3 + 2] + bv * outW1[k * 3 + 2];
            }
#pragma unroll
            for (int off = 16; off > 0; off >>= 1) {
                p0 += __shfl_down_sync(0xffffffffu, p0, off);
                p1 += __shfl_down_sync(0xffffffffu, p1, off);
                p2 += __shfl_down_sync(0xffffffffu, p2, off);
            }
            if (lane == 0) {
                size_t ro = (size_t)(base + r) * 3;
                out[ro + 0] = p0 + outb0[0] + outb1[0];
                out[ro + 1] = p1 + outb0[1] + outb1[1];
                out[ro + 2] = p2 + outb0[2] + outb1[2];
            }
        }
    }
}

// ============================================================================
extern "C" void kernel_launch(void* const* d_in, const int* in_sizes, int n_in,
                              void* d_out, int out_size)
{
    const float* coords = (const float*)d_in[0];
    const float* tokens = (const float*)d_in[1];
    const float* B_q    = (const float*)d_in[2];
    const float* B_l0   = (const float*)d_in[3];
    const float* B_l1   = (const float*)d_in[4];
    const float* qW     = (const float*)d_in[5];
    const float* qb     = (const float*)d_in[6];
    const float* toqW   = (const float*)d_in[7];
    const float* tokvW  = (const float*)d_in[8];
    const float* tooW   = (const float*)d_in[9];
    const float* toob   = (const float*)d_in[10];
    const float* bwW0   = (const float*)d_in[11];
    const float* bwb0   = (const float*)d_in[12];
    const float* bwW1   = (const float*)d_in[13];
    const float* bwb1   = (const float*)d_in[14];
    const float* modW0  = (const float*)d_in[15];
    const float* modb0  = (const float*)d_in[16];
    const float* modW1  = (const float*)d_in[17];
    const float* modb1  = (const float*)d_in[18];
    const float* hvW0   = (const float*)d_in[19];
    const float* hvb0   = (const float*)d_in[20];
    const float* outW0  = (const float*)d_in[21];
    const float* outb0  = (const float*)d_in[22];
    const float* outW1  = (const float*)d_in[23];
    const float* outb1  = (const float*)d_in[24];
    float* out = (float*)d_out;

    cudaFuncSetAttribute(k3_attn,  cudaFuncAttributeMaxDynamicSharedMemorySize, 131072);
    cudaFuncSetAttribute(k5_fused, cudaFuncAttributeMaxDynamicSharedMemorySize, 114688);

    k1_grid<<<HW / 16, 256>>>(coords, B_q, B_l0, B_l1, qW, qb, toqW,
                              bwW0, bwb0, bwW1, bwb1);
    k2_kv<<<dim3(MTOK / 16, BATCH), 256>>>(tokens, tokvW);
    k3_attn<<<dim3(HW / 256, 2, BATCH), 256, 131072>>>();
    k5_fused<<<(BATCH * HW) / 32, 256, 114688>>>(tooW, toob,
                                                 modW0, modb0, modW1, modb1,
                                                 hvW0, hvb0, outW0, outb0, outW1, outb1,
                                                 out);
}

// round 3
// speedup vs baseline: 1.5614x; 1.4018x over previous
#include <cuda_runtime.h>
#include <math.h>

#define HW      16384
#define BATCH   4
#define MTOK    256
#define HD      256
#define INNER   128
#define DH      64

#define TWO_PI 6.2831853071795864769f

typedef unsigned long long u64;

// ---- packed f32x2 helpers (sm_100+) ---------------------------------------
__device__ __forceinline__ u64 pack1(float v) {
    u64 r; asm("mov.b64 %0, {%1, %2};" : "=l"(r) : "f"(v), "f"(v)); return r;
}
__device__ __forceinline__ u64 ffma2(u64 a, u64 b, u64 c) {
    u64 d; asm("fma.rn.f32x2 %0, %1, %2, %3;" : "=l"(d) : "l"(a), "l"(b), "l"(c)); return d;
}
__device__ __forceinline__ u64 fmul2(u64 a, u64 b) {
    u64 d; asm("mul.rn.f32x2 %0, %1, %2;" : "=l"(d) : "l"(a), "l"(b)); return d;
}
__device__ __forceinline__ u64 fadd2(u64 a, u64 b) {
    u64 d; asm("add.rn.f32x2 %0, %1, %2;" : "=l"(d) : "l"(a), "l"(b)); return d;
}
__device__ __forceinline__ float2 unpack2(u64 v) {
    float2 f; asm("mov.b64 {%0, %1}, %2;" : "=f"(f.x), "=f"(f.y) : "l"(v)); return f;
}

// ---- cp.async helpers ------------------------------------------------------
__device__ __forceinline__ void cpa16(float* dst, const float* src) {
    unsigned d = (unsigned)__cvta_generic_to_shared(dst);
    asm volatile("cp.async.ca.shared.global [%0], [%1], 16;" :: "r"(d), "l"(src));
}
#define CPA_COMMIT() asm volatile("cp.async.commit_group;" ::: "memory")
#define CPA_WAIT0()  asm volatile("cp.async.wait_group 0;"  ::: "memory")

// ---------------- scratch (device globals; no runtime allocation) ----------
__device__ float g_q  [HW * INNER];
__device__ float g_h0 [HW * HD];
__device__ float g_h1 [HW * HD];
__device__ float g_t  [HW];
__device__ float g_k  [BATCH * 2 * MTOK * DH];
__device__ float g_v  [BATCH * 2 * MTOK * DH];
__device__ float g_o  [BATCH * HW * INNER];

// ============================================================================
// K1: grid-shared features. 16 rows / block, 256 threads.
// ============================================================================
__global__ void k1_grid(const float* __restrict__ coords,
                        const float* __restrict__ Bq,
                        const float* __restrict__ Bl0,
                        const float* __restrict__ Bl1,
                        const float* __restrict__ qW,  const float* __restrict__ qb,
                        const float* __restrict__ toqW,
                        const float* __restrict__ bwW0, const float* __restrict__ bwb0,
                        const float* __restrict__ bwW1, const float* __restrict__ bwb1)
{
    __shared__ float four[3][16][64];
    __shared__ float xq[16][256];
    const int tid  = threadIdx.x;
    const int base = blockIdx.x * 16;

    for (int it = tid; it < 3 * 16 * 32; it += 256) {
        int mat = it >> 9;
        int rem = it & 511;
        int r   = rem >> 5;
        int i   = rem & 31;
        float x = coords[(base + r) * 2 + 0];
        float y = coords[(base + r) * 2 + 1];
        const float* Bm = (mat == 0) ? Bq : (mat == 1 ? Bl0 : Bl1);
        float proj = TWO_PI * (x * Bm[i * 2] + y * Bm[i * 2 + 1]);
        float s, c;
        sincosf(proj, &s, &c);
        four[mat][r][i]      = c;
        four[mat][r][i + 32] = s;
    }
    if (tid < 16) {
        float x = coords[(base + tid) * 2 + 0];
        float y = coords[(base + tid) * 2 + 1];
        int row = (int)(x * 16.0f); row = min(max(row, 0), 15);
        int col = (int)(y * 16.0f); col = min(max(col, 0), 15);
        g_t[base + tid] = (float)(row * 16 + col) * (1.0f / 256.0f);
    }
    __syncthreads();

    {
        const int j = tid;
        float acc[16];
#pragma unroll
        for (int r = 0; r < 16; r++) acc[r] = 0.f;
        for (int k = 0; k < 64; k++) {
            float w = qW[k * 256 + j];
#pragma unroll
            for (int r = 0; r < 16; r++) acc[r] = fmaf(four[0][r][k], w, acc[r]);
        }
        float b = qb[j];
#pragma unroll
        for (int r = 0; r < 16; r++) xq[r][j] = fmaxf(acc[r] + b, 0.f);
    }
    __syncthreads();

    {
        const int j    = tid & 127;
        const int half = tid >> 7;
        float acc[8];
#pragma unroll
        for (int r = 0; r < 8; r++) acc[r] = 0.f;
        for (int k = 0; k < 256; k++) {
            float w = toqW[k * 128 + j];
#pragma unroll
            for (int r = 0; r < 8; r++) acc[r] = fmaf(xq[half * 8 + r][k], w, acc[r]);
        }
#pragma unroll
        for (int r = 0; r < 8; r++) g_q[(base + half * 8 + r) * 128 + j] = acc[r];
    }

    {
        const int j = tid;
        float a0[16], a1[16];
#pragma unroll
        for (int r = 0; r < 16; r++) { a0[r] = 0.f; a1[r] = 0.f; }
        for (int k = 0; k < 64; k++) {
            float w0 = bwW0[k * 256 + j];
            float w1 = bwW1[k * 256 + j];
#pragma unroll
            for (int r = 0; r < 16; r++) {
                a0[r] = fmaf(four[1][r][k], w0, a0[r]);
                a1[r] = fmaf(four[2][r][k], w1, a1[r]);
            }
        }
        float b0 = bwb0[j], b1 = bwb1[j];
#pragma unroll
        for (int r = 0; r < 16; r++) {
            g_h0[(base + r) * 256 + j] = fmaxf(a0[r] + b0, 0.f);
            g_h1[(base + r) * 256 + j] = fmaxf(a1[r] + b1, 0.f);
        }
    }
}

// ============================================================================
// K2: kv = tokens @ tokvW -> per-head k / v.
// ============================================================================
__global__ void k2_kv(const float* __restrict__ tokens,
                      const float* __restrict__ tokvW)
{
    __shared__ float tok[16][256];
    const int tile = blockIdx.x;
    const int b    = blockIdx.y;
    const int tid  = threadIdx.x;

    const float* tb = tokens + (b * MTOK + tile * 16) * 256;
    for (int i = tid; i < 16 * 256; i += 256) tok[i >> 8][i & 255] = tb[i];
    __syncthreads();

    const int j = tid;
    float acc[16];
#pragma unroll
    for (int r = 0; r < 16; r++) acc[r] = 0.f;
    for (int k = 0; k < 256; k++) {
        float w = tokvW[k * 256 + j];
#pragma unroll
        for (int r = 0; r < 16; r++) acc[r] = fmaf(tok[r][k], w, acc[r]);
    }
#pragma unroll
    for (int r = 0; r < 16; r++) {
        int m = tile * 16 + r;
        if (j < 128) {
            int h = j >> 6, d = j & 63;
            g_k[((b * 2 + h) * MTOK + m) * DH + d] = acc[r];
        } else {
            int j2 = j - 128;
            int h = j2 >> 6, d = j2 & 63;
            g_v[((b * 2 + h) * MTOK + m) * DH + d] = acc[r];
        }
    }
}

// ============================================================================
// K3: attention with spatial bias. 256 threads/block, f32x2 math.
// ============================================================================
__global__ void __launch_bounds__(256) k3_attn()
{
    extern __shared__ float sm[];
    float* ks = sm;
    float* vs = sm + MTOK * DH;

    const int h   = blockIdx.y;
    const int b   = blockIdx.z;
    const int tid = threadIdx.x;

    const float* kg = g_k + (b * 2 + h) * MTOK * DH;
    const float* vg = g_v + (b * 2 + h) * MTOK * DH;
    for (int i = tid * 4; i < MTOK * DH; i += 256 * 4) {
        *(float4*)&ks[i] = *(const float4*)&kg[i];
        *(float4*)&vs[i] = *(const float4*)&vg[i];
    }
    __syncthreads();

    const int row = blockIdx.x * 256 + tid;
    u64 q2[32];
    {
        const ulonglong2* qp = (const ulonglong2*)(g_q + row * 128 + h * 64);
#pragma unroll
        for (int i = 0; i < 16; i++) { ulonglong2 t = qp[i]; q2[2*i] = t.x; q2[2*i+1] = t.y; }
    }
    const float tt = g_t[row];

    u64 acc[32];
#pragma unroll
    for (int i = 0; i < 32; i++) acc[i] = 0ULL;
    float Mx = -1e30f, S = 0.f;

    for (int m = 0; m < 256; m++) {
        const ulonglong2* kp = (const ulonglong2*)&ks[m * 64];
        u64 sA = 0, sB = 0, sC = 0, sD = 0;
#pragma unroll
        for (int i = 0; i < 16; i += 2) {
            ulonglong2 k0 = kp[i];
            ulonglong2 k1 = kp[i + 1];
            sA = ffma2(q2[2*i    ], k0.x, sA);
            sB = ffma2(q2[2*i + 1], k0.y, sB);
            sC = ffma2(q2[2*i + 2], k1.x, sC);
            sD = ffma2(q2[2*i + 3], k1.y, sD);
        }
        float2 sf = unpack2(fadd2(fadd2(sA, sB), fadd2(sC, sD)));
        float pos  = ((float)m + 0.5f) * (1.0f / 256.0f);
        float diff = tt - pos;
        float s = (sf.x + sf.y) * 0.125f - 10.0f * diff * diff;

        if (s > Mx) {
            float corr = __expf(Mx - s);
            S *= corr;
            u64 cp = pack1(corr);
#pragma unroll
            for (int i = 0; i < 32; i++) acc[i] = fmul2(acc[i], cp);
            Mx = s;
        }
        float p = __expf(s - Mx);
        S += p;
        u64 pp = pack1(p);
        const ulonglong2* vp = (const ulonglong2*)&vs[m * 64];
#pragma unroll
        for (int i = 0; i < 16; i++) {
            ulonglong2 v0 = vp[i];
            acc[2*i    ] = ffma2(pp, v0.x, acc[2*i    ]);
            acc[2*i + 1] = ffma2(pp, v0.y, acc[2*i + 1]);
        }
    }

    float inv = 1.0f / S;
    float* og = g_o + ((size_t)b * HW + row) * 128 + h * 64;
#pragma unroll
    for (int i = 0; i < 32; i++) {
        float2 f = unpack2(acc[i]);
        float2 o2; o2.x = f.x * inv; o2.y = f.y * inv;
        *(float2*)&og[2 * i] = o2;
    }
}

// ============================================================================
// K5 v3: fully fused MLP chain, 64 rows/block, 256 threads.
// Weights staged through SMEM (cp.async double buffer, 16-k chunks).
// Thread tile: 8 rows x 8 cols. All inner-loop operands from SMEM.
// ============================================================================

// chunk copiers: 16 k-rows of weights into smem buffer
__device__ __forceinline__ void copy_chunk_single(float* dst, const float* W, int k0, int tid)
{
#pragma unroll
    for (int it = 0; it < 4; it++) {
        int f  = it * 256 + tid;     // float4 id (1024 total)
        int k  = f >> 6;
        int c4 = f & 63;
        cpa16(dst + k * 256 + c4 * 4, W + (k0 + k) * 256 + c4 * 4);
    }
}
__device__ __forceinline__ void copy_chunk_dual(float* dst, const float* W0, const float* W1,
                                                int k0, int tid)
{
#pragma unroll
    for (int it = 0; it < 8; it++) {
        int f   = it * 256 + tid;    // float4 id (2048 total)
        int k   = f >> 7;
        int rem = f & 127;
        int mat = rem >> 6;
        int c4  = rem & 63;
        const float* src = (mat ? W1 : W0) + (k0 + k) * 256 + c4 * 4;
        cpa16(dst + k * 512 + mat * 256 + c4 * 4, src);
    }
}

__device__ __forceinline__ void gemm16_single(const float* sIn, int lda, int k0,
                                              const float* wb, int r0, int c0, u64* a)
{
#pragma unroll
    for (int kk = 0; kk < 16; kk++) {
        const float* wr = wb + kk * 256;
        ulonglong2 wa = *(const ulonglong2*)(wr + c0);
        ulonglong2 wv = *(const ulonglong2*)(wr + c0 + 4);
#pragma unroll
        for (int r = 0; r < 8; r++) {
            u64 p = pack1(sIn[(r0 + r) * lda + k0 + kk]);
            a[r*4+0] = ffma2(p, wa.x, a[r*4+0]);
            a[r*4+1] = ffma2(p, wa.y, a[r*4+1]);
            a[r*4+2] = ffma2(p, wv.x, a[r*4+2]);
            a[r*4+3] = ffma2(p, wv.y, a[r*4+3]);
        }
    }
}

__device__ __forceinline__ void gemm16_dual(const float* sIn, int k0,
                                            const float* wb, int r0, int c0,
                                            u64* a0, u64* a1)
{
#pragma unroll
    for (int kk = 0; kk < 16; kk++) {
        const float* wr = wb + kk * 512;
        ulonglong2 w0a = *(const ulonglong2*)(wr + c0);
        ulonglong2 w0b = *(const ulonglong2*)(wr + c0 + 4);
        ulonglong2 w1a = *(const ulonglong2*)(wr + 256 + c0);
        ulonglong2 w1b = *(const ulonglong2*)(wr + 256 + c0 + 4);
#pragma unroll
        for (int r = 0; r < 8; r++) {
            u64 p = pack1(sIn[(r0 + r) * 256 + k0 + kk]);
            a0[r*4+0] = ffma2(p, w0a.x, a0[r*4+0]);
            a0[r*4+1] = ffma2(p, w0a.y, a0[r*4+1]);
            a0[r*4+2] = ffma2(p, w0b.x, a0[r*4+2]);
            a0[r*4+3] = ffma2(p, w0b.y, a0[r*4+3]);
            a1[r*4+0] = ffma2(p, w1a.x, a1[r*4+0]);
            a1[r*4+1] = ffma2(p, w1a.y, a1[r*4+1]);
            a1[r*4+2] = ffma2(p, w1b.x, a1[r*4+2]);
            a1[r*4+3] = ffma2(p, w1b.y, a1[r*4+3]);
        }
    }
}

__global__ void __launch_bounds__(256, 1) k5_v3(
    const float* __restrict__ tooW,  const float* __restrict__ toob,
    const float* __restrict__ modW0, const float* __restrict__ modb0,
    const float* __restrict__ modW1, const float* __restrict__ modb1,
    const float* __restrict__ hvW0,  const float* __restrict__ hvb0,
    const float* __restrict__ outW0, const float* __restrict__ outb0,
    const float* __restrict__ outW1, const float* __restrict__ outb1,
    float* __restrict__ out)
{
    extern __shared__ float smf[];
    float* sA = smf;              // 64x256 floats (o input 64x128, then x, then hv1)
    float* sB = smf + 16384;      // 64x256 (mod, then m0)
    float* sW = smf + 32768;      // 2 x 8192 weight chunk buffers

    const int tid  = threadIdx.x;
    const int warp = tid >> 5, lane = tid & 31;
    const int r0   = warp * 8;
    const int c0   = lane * 8;
    const int base = blockIdx.x * 64;
    const int hwb  = base & (HW - 1);

    // load o tile (64x128) into sA; prefetch first tooW chunk
    for (int i = tid * 4; i < 64 * 128; i += 1024)
        *(float4*)&sA[i] = *(const float4*)&g_o[(size_t)base * 128 + i];
    copy_chunk_single(sW, tooW, 0, tid);
    CPA_COMMIT();
    CPA_WAIT0();
    __syncthreads();

    // ---- stage 0: mod = o @ tooW + toob  (K=128, 8 chunks) ----
    {
        u64 a[32];
#pragma unroll
        for (int i = 0; i < 32; i++) a[i] = 0ULL;
        for (int c = 0; c < 8; c++) {
            if (c < 7) { copy_chunk_single(sW + ((c+1)&1)*8192, tooW, (c+1)*16, tid); CPA_COMMIT(); }
            gemm16_single(sA, 128, c * 16, sW + (c&1)*8192, r0, c0, a);
            CPA_WAIT0();
            __syncthreads();
        }
        // prefetch stage-1 chunk 0
        copy_chunk_dual(sW, modW0, modW1, 0, tid);
        CPA_COMMIT();

        ulonglong2 ba = *(const ulonglong2*)(toob + c0);
        ulonglong2 bb = *(const ulonglong2*)(toob + c0 + 4);
#pragma unroll
        for (int r = 0; r < 8; r++) {
            ulonglong2 o1, o2;
            o1.x = fadd2(a[r*4+0], ba.x); o1.y = fadd2(a[r*4+1], ba.y);
            o2.x = fadd2(a[r*4+2], bb.x); o2.y = fadd2(a[r*4+3], bb.y);
            *(ulonglong2*)&sB[(r0 + r) * 256 + c0]     = o1;
            *(ulonglong2*)&sB[(r0 + r) * 256 + c0 + 4] = o2;
        }
        CPA_WAIT0();
        __syncthreads();
    }

    // ---- stage 1: dual GEMM mod@modW0 / mod@modW1, combine with h0/h1 ----
    {
        u64 a0[32], a1[32];
#pragma unroll
        for (int i = 0; i < 32; i++) { a0[i] = 0ULL; a1[i] = 0ULL; }
        for (int c = 0; c < 16; c++) {
            if (c < 15) { copy_chunk_dual(sW + ((c+1)&1)*8192, modW0, modW1, (c+1)*16, tid); CPA_COMMIT(); }
            gemm16_dual(sB, c * 16, sW + (c&1)*8192, r0, c0, a0, a1);
            CPA_WAIT0();
            __syncthreads();
        }
        // prefetch stage-2 chunk 0
        copy_chunk_single(sW, hvW0, 0, tid);
        CPA_COMMIT();

        float4 b0a = *(const float4*)(modb0 + c0);
        float4 b0b = *(const float4*)(modb0 + c0 + 4);
        float4 b1a = *(const float4*)(modb1 + c0);
        float4 b1b = *(const float4*)(modb1 + c0 + 4);
        float bs0[8] = {b0a.x,b0a.y,b0a.z,b0a.w,b0b.x,b0b.y,b0b.z,b0b.w};
        float bs1[8] = {b1a.x,b1a.y,b1a.z,b1a.w,b1b.x,b1b.y,b1b.z,b1b.w};
#pragma unroll
        for (int r = 0; r < 8; r++) {
            const float* h0p = &g_h0[(size_t)(hwb + r0 + r) * 256 + c0];
            const float* h1p = &g_h1[(size_t)(hwb + r0 + r) * 256 + c0];
            float4 h0a = *(const float4*)h0p,       h0b = *(const float4*)(h0p + 4);
            float4 h1a = *(const float4*)h1p,       h1b = *(const float4*)(h1p + 4);
            float h0v[8] = {h0a.x,h0a.y,h0a.z,h0a.w,h0b.x,h0b.y,h0b.z,h0b.w};
            float h1v[8] = {h1a.x,h1a.y,h1a.z,h1a.w,h1b.x,h1b.y,h1b.z,h1b.w};
            float m0v[8], xv[8];
#pragma unroll
            for (int c = 0; c < 4; c++) {
                float2 f0 = unpack2(a0[r*4+c]);
                float2 f1 = unpack2(a1[r*4+c]);
                float v00 = fmaxf(h0v[2*c]   + f0.x + bs0[2*c],   0.f);
                float v01 = fmaxf(h0v[2*c+1] + f0.y + bs0[2*c+1], 0.f);
                float v10 = fmaxf(h1v[2*c]   + f1.x + bs1[2*c],   0.f);
                float v11 = fmaxf(h1v[2*c+1] + f1.y + bs1[2*c+1], 0.f);
                m0v[2*c] = v00; m0v[2*c+1] = v01;
                xv[2*c]  = v00 + v10; xv[2*c+1] = v01 + v11;
            }
            *(float4*)&sB[(r0 + r) * 256 + c0]     = *(float4*)&m0v[0];
            *(float4*)&sB[(r0 + r) * 256 + c0 + 4] = *(float4*)&m0v[4];
            *(float4*)&sA[(r0 + r) * 256 + c0]     = *(float4*)&xv[0];
            *(float4*)&sA[(r0 + r) * 256 + c0 + 4] = *(float4*)&xv[4];
        }
        CPA_WAIT0();
        __syncthreads();
    }

    // ---- stage 2: hv1 = relu(x @ hvW0 + hvb0) -> sA (in place over x) ----
    {
        u64 a[32];
#pragma unroll
        for (int i = 0; i < 32; i++) a[i] = 0ULL;
        for (int c = 0; c < 16; c++) {
            if (c < 15) { copy_chunk_single(sW + ((c+1)&1)*8192, hvW0, (c+1)*16, tid); CPA_COMMIT(); }
            gemm16_single(sA, 256, c * 16, sW + (c&1)*8192, r0, c0, a);
            CPA_WAIT0();
            __syncthreads();
        }
        float4 bha = *(const float4*)(hvb0 + c0);
        float4 bhb = *(const float4*)(hvb0 + c0 + 4);
        float bh[8] = {bha.x,bha.y,bha.z,bha.w,bhb.x,bhb.y,bhb.z,bhb.w};
#pragma unroll
        for (int r = 0; r < 8; r++) {
            float hv[8];
#pragma unroll
            for (int c = 0; c < 4; c++) {
                float2 f = unpack2(a[r*4+c]);
                hv[2*c]   = fmaxf(f.x + bh[2*c],   0.f);
                hv[2*c+1] = fmaxf(f.y + bh[2*c+1], 0.f);
            }
            *(float4*)&sA[(r0 + r) * 256 + c0]     = *(float4*)&hv[0];
            *(float4*)&sA[(r0 + r) * 256 + c0 + 4] = *(float4*)&hv[4];
        }
        __syncthreads();
    }

    // ---- stage 3: out = m0@outW0 + hv1@outW1 + biases (warp reductions) ----
    {
#pragma unroll
        for (int rr = 0; rr < 8; rr++) {
            int r = r0 + rr;
            float p0 = 0.f, p1 = 0.f, p2 = 0.f;
            for (int k = lane; k < 256; k += 32) {
                float a  = sB[r * 256 + k];
                float bv = sA[r * 256 + k];
                p0 += a * outW0[k * 3 + 0] + bv * outW1[k * 3 + 0];
                p1 += a * outW0[k * 3 + 1] + bv * outW1[k * 3 + 1];
                p2 += a * outW0[k * 3 + 2] + bv * outW1[k * 3 + 2];
            }
#pragma unroll
            for (int off = 16; off > 0; off >>= 1) {
                p0 += __shfl_down_sync(0xffffffffu, p0, off);
                p1 += __shfl_down_sync(0xffffffffu, p1, off);
                p2 += __shfl_down_sync(0xffffffffu, p2, off);
            }
            if (lane == 0) {
                size_t ro = (size_t)(base + r) * 3;
                out[ro + 0] = p0 + outb0[0] + outb1[0];
                out[ro + 1] = p1 + outb0[1] + outb1[1];
                out[ro + 2] = p2 + outb0[2] + outb1[2];
            }
        }
    }
}

// ============================================================================
extern "C" void kernel_launch(void* const* d_in, const int* in_sizes, int n_in,
                              void* d_out, int out_size)
{
    const float* coords = (const float*)d_in[0];
    const float* tokens = (const float*)d_in[1];
    const float* B_q    = (const float*)d_in[2];
    const float* B_l0   = (const float*)d_in[3];
    const float* B_l1   = (const float*)d_in[4];
    const float* qW     = (const float*)d_in[5];
    const float* qb     = (const float*)d_in[6];
    const float* toqW   = (const float*)d_in[7];
    const float* tokvW  = (const float*)d_in[8];
    const float* tooW   = (const float*)d_in[9];
    const float* toob   = (const float*)d_in[10];
    const float* bwW0   = (const float*)d_in[11];
    const float* bwb0   = (const float*)d_in[12];
    const float* bwW1   = (const float*)d_in[13];
    const float* bwb1   = (const float*)d_in[14];
    const float* modW0  = (const float*)d_in[15];
    const float* modb0  = (const float*)d_in[16];
    const float* modW1  = (const float*)d_in[17];
    const float* modb1  = (const float*)d_in[18];
    const float* hvW0   = (const float*)d_in[19];
    const float* hvb0   = (const float*)d_in[20];
    const float* outW0  = (const float*)d_in[21];
    const float* outb0  = (const float*)d_in[22];
    const float* outW1  = (const float*)d_in[23];
    const float* outb1  = (const float*)d_in[24];
    float* out = (float*)d_out;

    cudaFuncSetAttribute(k3_attn, cudaFuncAttributeMaxDynamicSharedMemorySize, 131072);
    cudaFuncSetAttribute(k5_v3,   cudaFuncAttributeMaxDynamicSharedMemorySize, 196608);

    k1_grid<<<HW / 16, 256>>>(coords, B_q, B_l0, B_l1, qW, qb, toqW,
                              bwW0, bwb0, bwW1, bwb1);
    k2_kv<<<dim3(MTOK / 16, BATCH), 256>>>(tokens, tokvW);
    k3_attn<<<dim3(HW / 256, 2, BATCH), 256, 131072>>>();
    k5_v3<<<(BATCH * HW) / 64, 256, 196608>>>(tooW, toob,
                                              modW0, modb0, modW1, modb1,
                                              hvW0, hvb0, outW0, outb0, outW1, outb1,
                                              out);
}